// round 16
// baseline (speedup 1.0000x reference)
#include <cuda_runtime.h>
#include <cuda_bf16.h>
#include <cuda_fp16.h>
#include <cstdint>

#define NTOK 16384
#define DIN  512
#define NB   8
#define KR   4608                 // K = 512*9, single fp16 term
#define BK   64                   // K per stage = 128 bytes/row
#define NST  72                   // stages
#define STAGE_BYTES 49152         // A 32KB + B 16KB
#define CTA_M 256
#define CTA_N 128
#define FEAT_BLOCKS (NTOK / 8)    // 2048
#define PACK_BLOCKS ((512 * KR) / 256)  // 9216
#define NLUT 2048
#define LUT_NODES (NLUT + 1)      // 2049
#define LUT_F4 (LUT_NODES * 2)    // float4 entries
#define LUT_BYTES (LUT_F4 * 16)   // 65568

// Scratch (allocation-free)
__device__ __align__(16) unsigned short g_F[(size_t)NTOK * KR];
__device__ __align__(16) unsigned short g_W[(size_t)512 * KR];
__device__ __align__(16) float4 g_LUTg[LUT_F4];

__device__ __forceinline__ void cpa16(uint32_t dst, const void* src) {
    asm volatile("cp.async.cg.shared.global [%0], [%1], 16;" :: "r"(dst), "l"(src));
}
__device__ __forceinline__ void ldsm_x4(uint32_t* r, uint32_t addr) {
    asm volatile("ldmatrix.sync.aligned.m8n8.x4.shared.b16 {%0,%1,%2,%3}, [%4];"
                 : "=r"(r[0]), "=r"(r[1]), "=r"(r[2]), "=r"(r[3]) : "r"(addr));
}
__device__ __forceinline__ void mma_f16_f32(float* c, const uint32_t* a,
                                            uint32_t b0, uint32_t b1) {
    asm volatile("mma.sync.aligned.m16n8k16.row.col.f32.f16.f16.f32 "
                 "{%0,%1,%2,%3}, {%4,%5,%6,%7}, {%8,%9}, {%0,%1,%2,%3};"
                 : "+f"(c[0]), "+f"(c[1]), "+f"(c[2]), "+f"(c[3])
                 : "r"(a[0]), "r"(a[1]), "r"(a[2]), "r"(a[3]), "r"(b0), "r"(b1));
}

// ---------------------------------------------------------------------------
// Kernel 0: build spline+RBF lookup table over xn in [-6, 6]
// ---------------------------------------------------------------------------
__global__ void lut_kernel()
{
    const int k = blockIdx.x * blockDim.x + threadIdx.x;
    if (k >= LUT_NODES) return;
    const float xv = -6.0f + (float)k * (12.0f / NLUT);

    // cubic B-spline closed form
    const float p = (xv + 3.3f) * (1.0f / 0.6f);
    const float xh = (xv + 1.5f) * (7.0f / 3.0f);
    float c[8];
    #pragma unroll
    for (int j = 0; j < 8; j++) {
        const float r  = fabsf(p - (float)(j + 2));
        const float t2 = fmaxf(2.0f - r, 0.0f);
        const float t1 = fmaxf(1.0f - r, 0.0f);
        const float bj = (t2 * t2 * t2 - 4.0f * t1 * t1 * t1) * (1.0f / 6.0f);
        const float u  = xh - (float)j;
        c[j] = bj + __expf(-u * u);
    }
    float4 lo; lo.x = c[0]; lo.y = c[1]; lo.z = c[2]; lo.w = c[3];
    float4 hi; hi.x = c[4]; hi.y = c[5]; hi.z = c[6]; hi.w = c[7];
    g_LUTg[2 * k]     = lo;
    g_LUTg[2 * k + 1] = hi;
}

// ---------------------------------------------------------------------------
// Fused kernel 1+2: blocks [0, FEAT_BLOCKS) warp-per-token LN + LUT features;
// blocks [FEAT_BLOCKS, ...) pack weights.
// ---------------------------------------------------------------------------
__global__ __launch_bounds__(256)
void feat_pack_kernel(const float* __restrict__ x,
                      const float* __restrict__ gamma_,
                      const float* __restrict__ beta_,
                      const float* __restrict__ bw,
                      const float* __restrict__ sw)
{
    if (blockIdx.x >= FEAT_BLOCKS) {
        const int idx = (blockIdx.x - FEAT_BLOCKS) * 256 + threadIdx.x;
        const int o = idx / KR;
        const int k = idx % KR;
        const int j = k >> 9;
        const int d = k & 511;
        const float w = (j == 0) ? bw[(size_t)o * DIN + d]
                                 : sw[(size_t)o * (DIN * NB) + d * NB + (j - 1)];
        g_W[idx] = __half_as_ushort(__float2half_rn(w));
        return;
    }

    extern __shared__ float4 sLUT[];   // LUT_F4 entries

    // stage the LUT (L2-resident source)
    for (int i = threadIdx.x; i < LUT_F4; i += 256)
        sLUT[i] = g_LUTg[i];

    const int warp = threadIdx.x >> 5;
    const int l    = threadIdx.x & 31;
    const int tok  = blockIdx.x * 8 + warp;

    const float4* xr = reinterpret_cast<const float4*>(x + (size_t)tok * DIN);
    const float4* g4 = reinterpret_cast<const float4*>(gamma_);
    const float4* b4 = reinterpret_cast<const float4*>(beta_);

    float4 v[4];
    float s1 = 0.0f, s2 = 0.0f;
    #pragma unroll
    for (int i = 0; i < 4; i++) {
        v[i] = xr[l + 32 * i];
        s1 += v[i].x + v[i].y + v[i].z + v[i].w;
        s2 += v[i].x * v[i].x + v[i].y * v[i].y + v[i].z * v[i].z + v[i].w * v[i].w;
    }
    #pragma unroll
    for (int o = 16; o > 0; o >>= 1) {
        s1 += __shfl_xor_sync(0xffffffffu, s1, o);
        s2 += __shfl_xor_sync(0xffffffffu, s2, o);
    }
    const float mu   = s1 * (1.0f / DIN);
    const float var  = s2 * (1.0f / DIN) - mu * mu;
    const float rstd = rsqrtf(var + 1e-5f);

    __syncthreads();   // LUT staged

    unsigned short* row = g_F + (size_t)tok * KR;

    #pragma unroll
    for (int i = 0; i < 4; i++) {
        const float4 gg = g4[l + 32 * i];
        const float4 bb = b4[l + 32 * i];
        const float xns[4] = {
            (v[i].x - mu) * rstd * gg.x + bb.x,
            (v[i].y - mu) * rstd * gg.y + bb.y,
            (v[i].z - mu) * rstd * gg.z + bb.z,
            (v[i].w - mu) * rstd * gg.w + bb.w
        };
        float f[4][9];
        #pragma unroll
        for (int c = 0; c < 4; c++) {
            const float xn = xns[c];
            f[c][0] = fmaxf(xn, 0.0f);
            const float xc = fminf(fmaxf(xn, -6.0f), 6.0f);
            const float t  = (xc + 6.0f) * (NLUT / 12.0f);
            int   ii = (int)t; ii = (ii > NLUT - 1) ? (NLUT - 1) : ii;
            const float fr = t - (float)ii;
            const float4 a0 = sLUT[2 * ii];
            const float4 a1 = sLUT[2 * ii + 1];
            const float4 c0 = sLUT[2 * ii + 2];
            const float4 c1 = sLUT[2 * ii + 3];
            f[c][1] = a0.x + fr * (c0.x - a0.x);
            f[c][2] = a0.y + fr * (c0.y - a0.y);
            f[c][3] = a0.z + fr * (c0.z - a0.z);
            f[c][4] = a0.w + fr * (c0.w - a0.w);
            f[c][5] = a1.x + fr * (c1.x - a1.x);
            f[c][6] = a1.y + fr * (c1.y - a1.y);
            f[c][7] = a1.z + fr * (c1.z - a1.z);
            f[c][8] = a1.w + fr * (c1.w - a1.w);
        }

        const int dbase = 128 * i + 4 * l;
        #pragma unroll
        for (int j = 0; j < 9; j++) {
            ushort4 o4;
            o4.x = __half_as_ushort(__float2half_rn(f[0][j]));
            o4.y = __half_as_ushort(__float2half_rn(f[1][j]));
            o4.z = __half_as_ushort(__float2half_rn(f[2][j]));
            o4.w = __half_as_ushort(__float2half_rn(f[3][j]));
            *reinterpret_cast<ushort4*>(&row[j * 512 + dbase]) = o4;
        }
    }
}

// ---------------------------------------------------------------------------
// Kernel 3: fp16 mma.sync GEMM  C[16384][512] = A[16384][4608] * B^T
// R10-proven config: CTA 256x128, 512 threads, 16 warps (4M x 4N) of 64x32,
// BK=64 SW128, 4-stage cp.async, single-buffered frags (128 regs = full RF).
// ---------------------------------------------------------------------------
__global__ __launch_bounds__(512, 1)
void gemm_kernel(float* __restrict__ C)
{
    extern __shared__ char smem_raw[];
    uint32_t raw;
    asm("{ .reg .u64 t; cvta.to.shared.u64 t, %1; cvt.u32.u64 %0, t; }"
        : "=r"(raw) : "l"(smem_raw));
    const uint32_t base = (raw + 1023) & ~1023u;

    const int tid  = threadIdx.x;
    const int wid  = tid >> 5;
    const int lane = tid & 31;
    const int wm   = wid & 3;          // 0..3 along M (64 each)
    const int wn   = wid >> 2;         // 0..3 along N (32 each)
    const int bm   = blockIdx.y * CTA_M;
    const int bn   = blockIdx.x * CTA_N;

    const int ld_r0 = tid >> 3;        // 0..63
    const int ld_c  = tid & 7;

    const int rx  = lane & 7;
    const int hiA = lane >> 4;
    const int hiB = (lane >> 3) & 1;
    uint32_t aoff[4], boff[2];
    #pragma unroll
    for (int mt = 0; mt < 4; mt++)
        aoff[mt] = (uint32_t)(wm * 64 + mt * 16 + (lane & 15)) * 128u;
    #pragma unroll
    for (int pp = 0; pp < 2; pp++)
        boff[pp] = 32768u + (uint32_t)(wn * 32 + pp * 16 + (lane & 7) + ((lane >> 4) << 3)) * 128u;

    float acc[4][4][4];
    #pragma unroll
    for (int mt = 0; mt < 4; mt++)
        #pragma unroll
        for (int nt = 0; nt < 4; nt++)
            #pragma unroll
            for (int q = 0; q < 4; q++) acc[mt][nt][q] = 0.0f;

    uint32_t fa[4][4], fb[2][4];

    #define LOAD_STAGE(sidx, SBASE) do {                                        \
        const int ko_ = (sidx) * BK;                                            \
        _Pragma("unroll")                                                       \
        for (int i_ = 0; i_ < 4; i_++) {                                        \
            const int r_ = ld_r0 + i_ * 64;                                     \
            cpa16((SBASE) + r_ * 128 + ((ld_c ^ (r_ & 7)) << 4),                \
                  g_F + (size_t)(bm + r_) * KR + ko_ + ld_c * 8);               \
        }                                                                       \
        _Pragma("unroll")                                                       \
        for (int i_ = 0; i_ < 2; i_++) {                                        \
            const int r_ = ld_r0 + i_ * 64;                                     \
            cpa16((SBASE) + 32768u + r_ * 128 + ((ld_c ^ (r_ & 7)) << 4),       \
                  g_W + (size_t)(bn + r_) * KR + ko_ + ld_c * 8);               \
        }                                                                       \
    } while (0)

    #define STEP(sv, BUF) do {                                                  \
        const int s_ = (sv);                                                    \
        asm volatile("cp.async.wait_group 2;" ::: "memory");                    \
        __syncthreads();                                                        \
        const uint32_t SA_ = base + (uint32_t)(BUF) * STAGE_BYTES;              \
        if (s_ + 3 < NST) {                                                     \
            LOAD_STAGE(s_ + 3, base + (uint32_t)(((BUF) + 3) & 3) * STAGE_BYTES); \
        }                                                                       \
        asm volatile("cp.async.commit_group;" ::: "memory");                    \
        _Pragma("unroll")                                                       \
        for (int ks_ = 0; ks_ < 4; ks_++) {                                     \
            _Pragma("unroll")                                                   \
            for (int mt_ = 0; mt_ < 4; mt_++)                                   \
                ldsm_x4(fa[mt_], SA_ + aoff[mt_] +                              \
                        ((uint32_t)(((ks_ << 1) | hiA) ^ rx) << 4));            \
            _Pragma("unroll")                                                   \
            for (int pp_ = 0; pp_ < 2; pp_++)                                   \
                ldsm_x4(fb[pp_], SA_ + boff[pp_] +                              \
                        ((uint32_t)(((ks_ << 1) | hiB) ^ rx) << 4));            \
            _Pragma("unroll")                                                   \
            for (int mt_ = 0; mt_ < 4; mt_++)                                   \
                _Pragma("unroll")                                               \
                for (int nt_ = 0; nt_ < 4; nt_++) {                             \
                    const uint32_t b0_ = (nt_ & 1) ? fb[nt_ >> 1][2] : fb[nt_ >> 1][0]; \
                    const uint32_t b1_ = (nt_ & 1) ? fb[nt_ >> 1][3] : fb[nt_ >> 1][1]; \
                    mma_f16_f32(acc[mt_][nt_], fa[mt_], b0_, b1_);              \
                }                                                               \
        }                                                                       \
    } while (0)

    // prologue: stages 0..2 into bufs 0..2
    LOAD_STAGE(0, base);
    asm volatile("cp.async.commit_group;" ::: "memory");
    LOAD_STAGE(1, base + STAGE_BYTES);
    asm volatile("cp.async.commit_group;" ::: "memory");
    LOAD_STAGE(2, base + 2 * STAGE_BYTES);
    asm volatile("cp.async.commit_group;" ::: "memory");

    for (int t = 0; t < NST; t += 4) {
        STEP(t + 0, 0);
        STEP(t + 1, 1);
        STEP(t + 2, 2);
        STEP(t + 3, 3);
    }

    // epilogue: thread holds rows g, g+8 and cols 2tg, 2tg+1 per (mt, nt)
    const int g  = lane >> 2;
    const int tg = lane & 3;
    #pragma unroll
    for (int mt = 0; mt < 4; mt++) {
        const int row0 = bm + wm * 64 + mt * 16 + g;
        #pragma unroll
        for (int nt = 0; nt < 4; nt++) {
            const int col = bn + wn * 32 + nt * 8 + tg * 2;
            float2 v0; v0.x = acc[mt][nt][0]; v0.y = acc[mt][nt][1];
            float2 v1; v1.x = acc[mt][nt][2]; v1.y = acc[mt][nt][3];
            *(float2*)&C[(size_t)row0 * 512 + col]       = v0;
            *(float2*)&C[(size_t)(row0 + 8) * 512 + col] = v1;
        }
    }
}

// ---------------------------------------------------------------------------
extern "C" void kernel_launch(void* const* d_in, const int* in_sizes, int n_in,
                              void* d_out, int out_size)
{
    const float* x  = (const float*)d_in[0];
    const float* g  = (const float*)d_in[1];
    const float* bt = (const float*)d_in[2];
    const float* bw = (const float*)d_in[3];
    const float* sw = (const float*)d_in[4];
    float* out = (float*)d_out;

    const int SMEM_DYN = 1024 + 4 * STAGE_BYTES;
    cudaFuncSetAttribute(gemm_kernel, cudaFuncAttributeMaxDynamicSharedMemorySize, SMEM_DYN);
    cudaFuncSetAttribute(feat_pack_kernel, cudaFuncAttributeMaxDynamicSharedMemorySize, LUT_BYTES);

    lut_kernel<<<(LUT_NODES + 255) / 256, 256>>>();
    feat_pack_kernel<<<FEAT_BLOCKS + PACK_BLOCKS, 256, LUT_BYTES>>>(x, g, bt, bw, sw);
    gemm_kernel<<<dim3(512 / CTA_N, NTOK / CTA_M), 512, SMEM_DYN>>>(out);
}

// round 17
// speedup vs baseline: 1.1090x; 1.1090x over previous
#include <cuda_runtime.h>
#include <cuda_bf16.h>
#include <cuda_fp16.h>
#include <cstdint>

#define NTOK 16384
#define DIN  512
#define NB   8
#define KR   4608                 // K = 512*9, single fp16 term
#define BK   64                   // K per sub-stage = 128 bytes/row
#define NSUP 36                   // superstages (2 sub-stages each)
#define STAGE_BYTES 49152         // one sub-stage: A 32KB + B 16KB
#define SUPER_BYTES 98304         // two sub-stages
#define CTA_M 256
#define CTA_N 128
#define FEAT_BLOCKS (NTOK / 8)    // 2048
#define PACK_BLOCKS ((512 * KR) / 256)  // 9216

// Scratch (allocation-free), fp16 payloads
__device__ __align__(16) unsigned short g_F[(size_t)NTOK * KR];
__device__ __align__(16) unsigned short g_W[(size_t)512 * KR];

__device__ __forceinline__ void cpa16(uint32_t dst, const void* src) {
    asm volatile("cp.async.cg.shared.global [%0], [%1], 16;" :: "r"(dst), "l"(src));
}
__device__ __forceinline__ void ldsm_x4(uint32_t* r, uint32_t addr) {
    asm volatile("ldmatrix.sync.aligned.m8n8.x4.shared.b16 {%0,%1,%2,%3}, [%4];"
                 : "=r"(r[0]), "=r"(r[1]), "=r"(r[2]), "=r"(r[3]) : "r"(addr));
}
__device__ __forceinline__ void mma_f16_f32(float* c, const uint32_t* a,
                                            uint32_t b0, uint32_t b1) {
    asm volatile("mma.sync.aligned.m16n8k16.row.col.f32.f16.f16.f32 "
                 "{%0,%1,%2,%3}, {%4,%5,%6,%7}, {%8,%9}, {%0,%1,%2,%3};"
                 : "+f"(c[0]), "+f"(c[1]), "+f"(c[2]), "+f"(c[3])
                 : "r"(a[0]), "r"(a[1]), "r"(a[2]), "r"(a[3]), "r"(b0), "r"(b1));
}

// ---------------------------------------------------------------------------
// per-dim feature vector from normalized activation xn
// ---------------------------------------------------------------------------
__device__ __forceinline__ void features_of(float xn, float* feat) {
    const float p = (xn + 3.3f) * (1.0f / 0.6f);
    float b[8];
    #pragma unroll
    for (int j = 0; j < 8; j++) {
        const float r  = fabsf(p - (float)(j + 2));
        const float t2 = fmaxf(2.0f - r, 0.0f);
        const float t1 = fmaxf(1.0f - r, 0.0f);
        b[j] = (t2 * t2 * t2 - 4.0f * t1 * t1 * t1) * (1.0f / 6.0f);
    }
    const float xh = (xn + 1.5f) * (7.0f / 3.0f);
    feat[0] = fmaxf(xn, 0.0f);
    #pragma unroll
    for (int j = 0; j < NB; j++) {
        const float u = xh - (float)j;
        feat[1 + j] = b[j] + __expf(-u * u);
    }
}

// ---------------------------------------------------------------------------
// Fused kernel 1+2 (R14-proven): feat blocks + pack blocks, no dynamic smem
// ---------------------------------------------------------------------------
__global__ __launch_bounds__(256)
void feat_pack_kernel(const float* __restrict__ x,
                      const float* __restrict__ gamma_,
                      const float* __restrict__ beta_,
                      const float* __restrict__ bw,
                      const float* __restrict__ sw)
{
    if (blockIdx.x >= FEAT_BLOCKS) {
        const int idx = (blockIdx.x - FEAT_BLOCKS) * 256 + threadIdx.x;
        const int o = idx / KR;
        const int k = idx % KR;
        const int j = k >> 9;
        const int d = k & 511;
        const float w = (j == 0) ? bw[(size_t)o * DIN + d]
                                 : sw[(size_t)o * (DIN * NB) + d * NB + (j - 1)];
        g_W[idx] = __half_as_ushort(__float2half_rn(w));
        return;
    }

    const int warp = threadIdx.x >> 5;
    const int l    = threadIdx.x & 31;
    const int tok  = blockIdx.x * 8 + warp;

    const float4* xr = reinterpret_cast<const float4*>(x + (size_t)tok * DIN);
    const float4* g4 = reinterpret_cast<const float4*>(gamma_);
    const float4* b4 = reinterpret_cast<const float4*>(beta_);

    float4 v[4];
    float s1 = 0.0f, s2 = 0.0f;
    #pragma unroll
    for (int i = 0; i < 4; i++) {
        v[i] = xr[l + 32 * i];
        s1 += v[i].x + v[i].y + v[i].z + v[i].w;
        s2 += v[i].x * v[i].x + v[i].y * v[i].y + v[i].z * v[i].z + v[i].w * v[i].w;
    }
    #pragma unroll
    for (int o = 16; o > 0; o >>= 1) {
        s1 += __shfl_xor_sync(0xffffffffu, s1, o);
        s2 += __shfl_xor_sync(0xffffffffu, s2, o);
    }
    const float mu   = s1 * (1.0f / DIN);
    const float var  = s2 * (1.0f / DIN) - mu * mu;
    const float rstd = rsqrtf(var + 1e-5f);

    unsigned short* row = g_F + (size_t)tok * KR;

    #pragma unroll
    for (int i = 0; i < 4; i++) {
        const float4 gg = g4[l + 32 * i];
        const float4 bb = b4[l + 32 * i];
        const float xns[4] = {
            (v[i].x - mu) * rstd * gg.x + bb.x,
            (v[i].y - mu) * rstd * gg.y + bb.y,
            (v[i].z - mu) * rstd * gg.z + bb.z,
            (v[i].w - mu) * rstd * gg.w + bb.w
        };
        float f[4][9];
        #pragma unroll
        for (int c = 0; c < 4; c++) features_of(xns[c], f[c]);

        const int dbase = 128 * i + 4 * l;
        #pragma unroll
        for (int j = 0; j < 9; j++) {
            ushort4 o4;
            o4.x = __half_as_ushort(__float2half_rn(f[0][j]));
            o4.y = __half_as_ushort(__float2half_rn(f[1][j]));
            o4.z = __half_as_ushort(__float2half_rn(f[2][j]));
            o4.w = __half_as_ushort(__float2half_rn(f[3][j]));
            *reinterpret_cast<ushort4*>(&row[j * 512 + dbase]) = o4;
        }
    }
}

// ---------------------------------------------------------------------------
// Kernel 3: fp16 mma.sync GEMM  C[16384][512] = A[16384][4608] * B^T
// R10 tiling (CTA 256x128, 512 thr, 16 warps 4Mx4N of 64x32, BK=64 SW128,
// single-buffered frags) with SUPERSTAGE double-buffer: one barrier per
// 2 sub-stages, prefetch issued after the barrier (race-free).
// ---------------------------------------------------------------------------
__global__ __launch_bounds__(512, 1)
void gemm_kernel(float* __restrict__ C)
{
    extern __shared__ char smem_raw[];
    uint32_t raw;
    asm("{ .reg .u64 t; cvta.to.shared.u64 t, %1; cvt.u32.u64 %0, t; }"
        : "=r"(raw) : "l"(smem_raw));
    const uint32_t base = (raw + 1023) & ~1023u;

    const int tid  = threadIdx.x;
    const int wid  = tid >> 5;
    const int lane = tid & 31;
    const int wm   = wid & 3;          // 0..3 along M (64 each)
    const int wn   = wid >> 2;         // 0..3 along N (32 each)
    const int bm   = blockIdx.y * CTA_M;
    const int bn   = blockIdx.x * CTA_N;

    const int ld_r0 = tid >> 3;        // 0..63
    const int ld_c  = tid & 7;

    const int rx  = lane & 7;
    const int hiA = lane >> 4;
    const int hiB = (lane >> 3) & 1;
    uint32_t aoff[4], boff[2];
    #pragma unroll
    for (int mt = 0; mt < 4; mt++)
        aoff[mt] = (uint32_t)(wm * 64 + mt * 16 + (lane & 15)) * 128u;
    #pragma unroll
    for (int pp = 0; pp < 2; pp++)
        boff[pp] = 32768u + (uint32_t)(wn * 32 + pp * 16 + (lane & 7) + ((lane >> 4) << 3)) * 128u;

    float acc[4][4][4];
    #pragma unroll
    for (int mt = 0; mt < 4; mt++)
        #pragma unroll
        for (int nt = 0; nt < 4; nt++)
            #pragma unroll
            for (int q = 0; q < 4; q++) acc[mt][nt][q] = 0.0f;

    uint32_t fa[4][4], fb[2][4];

    #define LOAD_STAGE(sidx, SBASE) do {                                        \
        const int ko_ = (sidx) * BK;                                            \
        _Pragma("unroll")                                                       \
        for (int i_ = 0; i_ < 4; i_++) {                                        \
            const int r_ = ld_r0 + i_ * 64;                                     \
            cpa16((SBASE) + r_ * 128 + ((ld_c ^ (r_ & 7)) << 4),                \
                  g_F + (size_t)(bm + r_) * KR + ko_ + ld_c * 8);               \
        }                                                                       \
        _Pragma("unroll")                                                       \
        for (int i_ = 0; i_ < 2; i_++) {                                        \
            const int r_ = ld_r0 + i_ * 64;                                     \
            cpa16((SBASE) + 32768u + r_ * 128 + ((ld_c ^ (r_ & 7)) << 4),       \
                  g_W + (size_t)(bn + r_) * KR + ko_ + ld_c * 8);               \
        }                                                                       \
    } while (0)

    // compute the 4 ks-steps of one sub-stage buffer
    #define COMPUTE_BUF(SA_) do {                                               \
        _Pragma("unroll")                                                       \
        for (int ks_ = 0; ks_ < 4; ks_++) {                                     \
            _Pragma("unroll")                                                   \
            for (int mt_ = 0; mt_ < 4; mt_++)                                   \
                ldsm_x4(fa[mt_], (SA_) + aoff[mt_] +                            \
                        ((uint32_t)(((ks_ << 1) | hiA) ^ rx) << 4));            \
            _Pragma("unroll")                                                   \
            for (int pp_ = 0; pp_ < 2; pp_++)                                   \
                ldsm_x4(fb[pp_], (SA_) + boff[pp_] +                            \
                        ((uint32_t)(((ks_ << 1) | hiB) ^ rx) << 4));            \
            _Pragma("unroll")                                                   \
            for (int mt_ = 0; mt_ < 4; mt_++)                                   \
                _Pragma("unroll")                                               \
                for (int nt_ = 0; nt_ < 4; nt_++) {                             \
                    const uint32_t b0_ = (nt_ & 1) ? fb[nt_ >> 1][2] : fb[nt_ >> 1][0]; \
                    const uint32_t b1_ = (nt_ & 1) ? fb[nt_ >> 1][3] : fb[nt_ >> 1][1]; \
                    mma_f16_f32(acc[mt_][nt_], fa[mt_], b0_, b1_);              \
                }                                                               \
        }                                                                       \
    } while (0)

    // superstage u: wait load(u) -> sync -> prefetch u+1 -> compute both halves
    #define SUPERSTEP(uv, BUF) do {                                             \
        const int u_ = (uv);                                                    \
        asm volatile("cp.async.wait_group 0;" ::: "memory");                    \
        __syncthreads();                                                        \
        if (u_ + 1 < NSUP) {                                                    \
            const uint32_t NB_ = base + (uint32_t)(1 - (BUF)) * SUPER_BYTES;    \
            LOAD_STAGE(2 * u_ + 2, NB_);                                        \
            LOAD_STAGE(2 * u_ + 3, NB_ + STAGE_BYTES);                          \
            asm volatile("cp.async.commit_group;" ::: "memory");                \
        }                                                                       \
        const uint32_t S_ = base + (uint32_t)(BUF) * SUPER_BYTES;               \
        COMPUTE_BUF(S_);                                                        \
        COMPUTE_BUF(S_ + STAGE_BYTES);                                          \
    } while (0)

    // prologue: superstage 0 into buffer 0
    LOAD_STAGE(0, base);
    LOAD_STAGE(1, base + STAGE_BYTES);
    asm volatile("cp.async.commit_group;" ::: "memory");

    for (int u = 0; u < NSUP; u += 2) {
        SUPERSTEP(u + 0, 0);
        SUPERSTEP(u + 1, 1);
    }

    // epilogue: thread holds rows g, g+8 and cols 2tg, 2tg+1 per (mt, nt)
    const int g  = lane >> 2;
    const int tg = lane & 3;
    #pragma unroll
    for (int mt = 0; mt < 4; mt++) {
        const int row0 = bm + wm * 64 + mt * 16 + g;
        #pragma unroll
        for (int nt = 0; nt < 4; nt++) {
            const int col = bn + wn * 32 + nt * 8 + tg * 2;
            float2 v0; v0.x = acc[mt][nt][0]; v0.y = acc[mt][nt][1];
            float2 v1; v1.x = acc[mt][nt][2]; v1.y = acc[mt][nt][3];
            *(float2*)&C[(size_t)row0 * 512 + col]       = v0;
            *(float2*)&C[(size_t)(row0 + 8) * 512 + col] = v1;
        }
    }
}

// ---------------------------------------------------------------------------
extern "C" void kernel_launch(void* const* d_in, const int* in_sizes, int n_in,
                              void* d_out, int out_size)
{
    const float* x  = (const float*)d_in[0];
    const float* g  = (const float*)d_in[1];
    const float* bt = (const float*)d_in[2];
    const float* bw = (const float*)d_in[3];
    const float* sw = (const float*)d_in[4];
    float* out = (float*)d_out;

    const int SMEM_DYN = 1024 + 2 * SUPER_BYTES;   // 197632
    cudaFuncSetAttribute(gemm_kernel, cudaFuncAttributeMaxDynamicSharedMemorySize, SMEM_DYN);

    feat_pack_kernel<<<FEAT_BLOCKS + PACK_BLOCKS, 256>>>(x, g, bt, bw, sw);
    gemm_kernel<<<dim3(512 / CTA_N, NTOK / CTA_M), 512, SMEM_DYN>>>(out);
}